// round 1
// baseline (speedup 1.0000x reference)
#include <cuda_runtime.h>
#include <math.h>

// Self-convolution via shared-memory FFT.
// out[b,t] = sum_i x[b,i]*x[b,t-i], t in [0, 2L-2].
// N = 8192 >= 2L-1, so circular convolution == linear convolution.
// Forward DIF (natural -> bitrev) -> pointwise square (order-free) ->
// inverse DIT (bitrev -> natural). No bit-reversal permutation needed.

#define FFT_N     8192
#define SEQ_L     4096
#define OUT_L     (2 * SEQ_L - 1)   // 8191
#define NTHREADS  512

extern __shared__ float s_mem[];

__global__ void __launch_bounds__(NTHREADS, 1)
conv_self_fft_kernel(const float* __restrict__ x, float* __restrict__ out) {
    float* re   = s_mem;                       // FFT_N floats
    float* im   = s_mem + FFT_N;               // FFT_N floats
    float* twre = s_mem + 2 * FFT_N;           // FFT_N/2 floats
    float* twim = s_mem + 2 * FFT_N + FFT_N/2; // FFT_N/2 floats

    const int tid = threadIdx.x;
    const int b   = blockIdx.x;
    const float* xb = x + (size_t)b * SEQ_L;

    // Twiddle table: tw[k] = exp(-2*pi*i*k/N), k in [0, N/2)
    const float MINUS_TWO_PI_OVER_N = -6.28318530717958647692f / (float)FFT_N;
    #pragma unroll
    for (int k = tid; k < FFT_N / 2; k += NTHREADS) {
        float s, c;
        sincosf(MINUS_TWO_PI_OVER_N * (float)k, &s, &c);
        twre[k] = c;
        twim[k] = s;
    }

    // Load input (zero-padded), imaginary = 0
    #pragma unroll
    for (int i = tid; i < FFT_N; i += NTHREADS) {
        re[i] = (i < SEQ_L) ? xb[i] : 0.0f;
        im[i] = 0.0f;
    }
    __syncthreads();

    // ---- Forward FFT: DIF, natural-order input, bit-reversed output ----
    for (int len = FFT_N; len >= 2; len >>= 1) {
        const int half  = len >> 1;
        const int tstep = FFT_N / len;
        #pragma unroll
        for (int j = tid; j < FFT_N / 2; j += NTHREADS) {
            const int pos = j & (half - 1);
            const int i0  = ((j - pos) << 1) + pos;   // block*len + pos
            const int i1  = i0 + half;
            const float ar = re[i0], ai = im[i0];
            const float br = re[i1], bi = im[i1];
            const float dr = ar - br, di = ai - bi;
            const int   tw = pos * tstep;
            const float wr = twre[tw], wi = twim[tw];
            re[i0] = ar + br;
            im[i0] = ai + bi;
            re[i1] = dr * wr - di * wi;
            im[i1] = dr * wi + di * wr;
        }
        __syncthreads();
    }

    // ---- Pointwise square: Y = X^2 (valid in any consistent permutation) ----
    #pragma unroll
    for (int i = tid; i < FFT_N; i += NTHREADS) {
        const float r = re[i], q = im[i];
        re[i] = r * r - q * q;
        im[i] = 2.0f * r * q;
    }
    __syncthreads();

    // ---- Inverse FFT: DIT, bit-reversed input, natural-order output ----
    for (int len = 2; len <= FFT_N; len <<= 1) {
        const int half  = len >> 1;
        const int tstep = FFT_N / len;
        #pragma unroll
        for (int j = tid; j < FFT_N / 2; j += NTHREADS) {
            const int pos = j & (half - 1);
            const int i0  = ((j - pos) << 1) + pos;
            const int i1  = i0 + half;
            const int  tw = pos * tstep;
            const float wr =  twre[tw];
            const float wi = -twim[tw];               // conjugate for inverse
            const float br = re[i1], bi = im[i1];
            const float tr = br * wr - bi * wi;
            const float ti = br * wi + bi * wr;
            const float ar = re[i0], ai = im[i0];
            re[i0] = ar + tr;
            im[i0] = ai + ti;
            re[i1] = ar - tr;
            im[i1] = ai - ti;
        }
        __syncthreads();
    }

    // ---- Write real part scaled by 1/N ----
    const float invN = 1.0f / (float)FFT_N;
    float* ob = out + (size_t)b * OUT_L;
    #pragma unroll
    for (int i = tid; i < OUT_L; i += NTHREADS) {
        ob[i] = re[i] * invN;
    }
}

extern "C" void kernel_launch(void* const* d_in, const int* in_sizes, int n_in,
                              void* d_out, int out_size) {
    (void)in_sizes; (void)n_in; (void)out_size;
    const float* x = (const float*)d_in[0];
    float* out = (float*)d_out;

    const int smem_bytes = (2 * FFT_N + FFT_N) * (int)sizeof(float); // re+im+twiddles = 96 KB
    cudaFuncSetAttribute(conv_self_fft_kernel,
                         cudaFuncAttributeMaxDynamicSharedMemorySize, smem_bytes);

    conv_self_fft_kernel<<<128, NTHREADS, smem_bytes>>>(x, out);
}

// round 2
// speedup vs baseline: 4.4655x; 4.4655x over previous
#include <cuda_runtime.h>
#include <math.h>

// Self-convolution via real-packed shared-memory FFT.
// out[b,t] = sum_i x[b,i]*x[b,t-i], N=8192-point conv realized as a
// M=4096-point complex FFT of packed z[m]=x[2m]+i*x[2m+1]:
//   fwd DIF (nat->bitrev, fused 2-stage passes)
//   middle: untangle X from Z, square (Y=X^2), repack Zi for inverse
//           (pairing k<->M-k is a block-reversal in bitrev coords)
//   inv DIT (bitrev->nat, fused), y[2m]=Re(zi), y[2m+1]=Im(zi), scale 1/M.

#define SEQ_L   4096
#define OUT_L   (2 * SEQ_L - 1)     // 8191
#define FFT_M   4096                // packed complex FFT size
#define NT      1024

#define IDX(a)  ((a) + ((a) >> 4))  // smem bank-conflict padding

#define RE_SZ   (FFT_M + (FFT_M >> 4))          // 4352
#define TW_SZ   ((FFT_M/2) + ((FFT_M/2) >> 4))  // 2176

extern __shared__ float s_mem[];

__global__ void __launch_bounds__(NT, 1)
conv_self_rfft_kernel(const float* __restrict__ x, float* __restrict__ out) {
    float* re   = s_mem;
    float* im   = s_mem + RE_SZ;
    float* twre = s_mem + 2 * RE_SZ;
    float* twim = s_mem + 2 * RE_SZ + TW_SZ;

    const int tid = threadIdx.x;
    const int b   = blockIdx.x;

    // Twiddles: tw[t] = exp(-2*pi*i*t/M), t in [0, M/2)
    const float W_ANG = -6.28318530717958647692f / (float)FFT_M;
    for (int t = tid; t < FFT_M / 2; t += NT) {
        float s, c;
        sincosf(W_ANG * (float)t, &s, &c);
        twre[IDX(t)] = c;
        twim[IDX(t)] = s;
    }

    // Load packed input: z[m] = x[2m] + i*x[2m+1]; zero-pad m >= L/2
    const float2* xb2 = (const float2*)(x + (size_t)b * SEQ_L);
    for (int m = tid; m < FFT_M; m += NT) {
        if (m < SEQ_L / 2) {
            float2 v = xb2[m];
            re[IDX(m)] = v.x;
            im[IDX(m)] = v.y;
        } else {
            re[IDX(m)] = 0.0f;
            im[IDX(m)] = 0.0f;
        }
    }
    __syncthreads();

    // ---- Forward DIF, fused 2 stages per pass: len in {4096,1024,256,64,16,4}
    #pragma unroll
    for (int len = FFT_M; len >= 4; len >>= 2) {
        const int q  = len >> 2;
        const int h  = len >> 1;
        const int st = FFT_M / len;

        const int pos  = tid & (q - 1);
        const int base = ((tid - pos) << 2) + pos;
        const int a0 = IDX(base), a1 = IDX(base + q), a2 = IDX(base + h), a3 = IDX(base + 3 * q);

        const float Ar = re[a0], Ai = im[a0];
        const float Br = re[a1], Bi = im[a1];
        const float Cr = re[a2], Ci = im[a2];
        const float Dr = re[a3], Di = im[a3];

        const int t1 = pos * st;
        const float w1r = twre[IDX(t1)], w1i = twim[IDX(t1)];
        // twiddle at t1 + M/4 == -i * W1
        const float wbr = w1i, wbi = -w1r;
        const int t2 = 2 * t1;
        const float w2r = twre[IDX(t2)], w2i = twim[IDX(t2)];

        // stage 1 (len): (A,C) and (B,D)
        const float A2r = Ar + Cr, A2i = Ai + Ci;
        float ur = Ar - Cr, ui = Ai - Ci;
        const float C2r = ur * w1r - ui * w1i;
        const float C2i = ur * w1i + ui * w1r;
        const float B2r = Br + Dr, B2i = Bi + Di;
        ur = Br - Dr; ui = Bi - Di;
        const float D2r = ur * wbr - ui * wbi;
        const float D2i = ur * wbi + ui * wbr;

        // stage 2 (len/2): (A2,B2) and (C2,D2), shared twiddle W2
        re[a0] = A2r + B2r;  im[a0] = A2i + B2i;
        ur = A2r - B2r; ui = A2i - B2i;
        re[a1] = ur * w2r - ui * w2i;
        im[a1] = ur * w2i + ui * w2r;
        re[a2] = C2r + D2r;  im[a2] = C2i + D2i;
        ur = C2r - D2r; ui = C2i - D2i;
        re[a3] = ur * w2r - ui * w2i;
        im[a3] = ur * w2i + ui * w2r;

        __syncthreads();
    }

    // ---- Middle: untangle + square + repack (data in bit-reversed order) ----
    const float N_ANG = -6.28318530717958647692f / (float)(2 * FFT_M);
    for (int m = tid; m < FFT_M / 2; m += NT) {
        if (m == 0) {
            // kb=0: k=0 -> X[0]=E+O, X[M]=E-O (real)
            float zr = re[IDX(0)], zi_ = im[IDX(0)];
            float P = zr + zi_, Q = zr - zi_;
            float P2 = P * P, Q2 = Q * Q;
            re[IDX(0)] = 0.5f * (P2 + Q2);
            im[IDX(0)] = 0.5f * (P2 - Q2);
            // kb=1: k=M/2 self-paired -> Zi = (E^2-O^2, 2EO)
            zr = re[IDX(1)]; zi_ = im[IDX(1)];
            re[IDX(1)] = zr * zr - zi_ * zi_;
            im[IDX(1)] = 2.0f * zr * zi_;
        } else {
            const int msb = 1 << (31 - __clz(m));
            const int kb = m + msb;                 // bitrev pos of k
            const int pb = 6 * msb - 1 - kb;        // bitrev pos of M-k
            const int k  = __brev((unsigned)kb) >> 20;  // natural k (12-bit)

            float wr, wi;
            sincosf(N_ANG * (float)k, &wi, &wr);    // W_N^k = (cos, sin)

            const float zkr = re[IDX(kb)], zki = im[IDX(kb)];
            const float zmr = re[IDX(pb)], zmi = im[IDX(pb)];

            const float Er = 0.5f * (zkr + zmr);
            const float Ei = 0.5f * (zki - zmi);
            const float Or = 0.5f * (zki + zmi);
            const float Oi = 0.5f * (zmr - zkr);

            const float WOr = Or * wr - Oi * wi;
            const float WOi = Or * wi + Oi * wr;

            const float Pr = Er + WOr, Pi = Ei + WOi;   // X[k]
            const float Qr = Er - WOr, Qi = Ei - WOi;   // X[k+M] = conj(X[M-k])

            const float P2r = Pr * Pr - Pi * Pi, P2i = 2.0f * Pr * Pi;
            const float Q2r = Qr * Qr - Qi * Qi, Q2i = 2.0f * Qr * Qi;

            const float Epr = 0.5f * (P2r + Q2r);
            const float Epi = 0.5f * (P2i + Q2i);
            const float Sr  = 0.5f * (P2r - Q2r);
            const float Si  = 0.5f * (P2i - Q2i);
            // O' = conj(W) * S
            const float Opr = Sr * wr + Si * wi;
            const float Opi = Si * wr - Sr * wi;

            re[IDX(kb)] = Epr - Opi;                 // Zi[k]
            im[IDX(kb)] = Epi + Opr;
            re[IDX(pb)] = Epr + Opi;                 // Zi[M-k] = conj(E')+i*conj(O')
            im[IDX(pb)] = Opr - Epi;
        }
    }
    __syncthreads();

    // ---- Inverse DIT, fused: lenBig in {4,16,64,256,1024,4096} ----
    #pragma unroll
    for (int lenBig = 4; lenBig <= FFT_M; lenBig <<= 2) {
        const int q  = lenBig >> 2;
        const int h  = lenBig >> 1;
        const int sb = FFT_M / lenBig;

        const int pos  = tid & (q - 1);
        const int base = ((tid - pos) << 2) + pos;
        const int a0 = IDX(base), a1 = IDX(base + q), a2 = IDX(base + h), a3 = IDX(base + 3 * q);

        const float Ar = re[a0], Ai = im[a0];
        const float Br = re[a1], Bi = im[a1];
        const float Cr = re[a2], Ci = im[a2];
        const float Dr = re[a3], Di = im[a3];

        const int tb = pos * sb;
        const float wbr = twre[IDX(tb)], wbi = twim[IDX(tb)];
        const int ts = 2 * tb;
        const float wsr = twre[IDX(ts)], wsi = twim[IDX(ts)];

        // small stage (half=q), conj twiddle Ws
        float tr = Br * wsr + Bi * wsi;
        float ti = Bi * wsr - Br * wsi;
        const float A1r = Ar + tr, A1i = Ai + ti;
        const float B1r = Ar - tr, B1i = Ai - ti;
        tr = Dr * wsr + Di * wsi;
        ti = Di * wsr - Dr * wsi;
        const float C1r = Cr + tr, C1i = Ci + ti;
        const float D1r = Cr - tr, D1i = Ci - ti;

        // big stage (half=h): conj(W^tb) and conj(W^{tb+M/4}) = (wbi, wbr)
        tr = C1r * wbr + C1i * wbi;
        ti = C1i * wbr - C1r * wbi;
        re[a0] = A1r + tr;  im[a0] = A1i + ti;
        re[a2] = A1r - tr;  im[a2] = A1i - ti;
        // conj(-i*Wb) = i*conj(Wb) -> multiply D1 by (wbi + i*wbr)... as complex (wbi, wbr)
        tr = D1r * wbi - D1i * wbr;
        ti = D1r * wbr + D1i * wbi;
        re[a1] = B1r + tr;  im[a1] = B1i + ti;
        re[a3] = B1r - tr;  im[a3] = B1i - ti;

        __syncthreads();
    }

    // ---- Store: y[2m]=Re(zi[m])/M, y[2m+1]=Im(zi[m])/M ----
    const float invM = 1.0f / (float)FFT_M;
    float* ob = out + (size_t)b * OUT_L;
    for (int m = tid; m < FFT_M; m += NT) {
        const int a = IDX(m);
        ob[2 * m] = re[a] * invM;
        if (2 * m + 1 < OUT_L)
            ob[2 * m + 1] = im[a] * invM;
    }
}

extern "C" void kernel_launch(void* const* d_in, const int* in_sizes, int n_in,
                              void* d_out, int out_size) {
    (void)in_sizes; (void)n_in; (void)out_size;
    const float* x = (const float*)d_in[0];
    float* out = (float*)d_out;

    const int smem_bytes = (2 * RE_SZ + 2 * TW_SZ) * (int)sizeof(float);  // ~51 KB
    cudaFuncSetAttribute(conv_self_rfft_kernel,
                         cudaFuncAttributeMaxDynamicSharedMemorySize, smem_bytes);

    conv_self_rfft_kernel<<<128, NT, smem_bytes>>>(x, out);
}

// round 3
// speedup vs baseline: 5.0784x; 1.1373x over previous
#include <cuda_runtime.h>
#include <math.h>

// Self-convolution via real-packed shared-memory FFT, radix-8 fused passes.
// out[b,t] = sum_i x[b,i]*x[b,t-i]; 8192-pt conv via M=4096 complex FFT of
// z[m]=x[2m]+i*x[2m+1]. Fwd DIF (nat->bitrev, 4 radix-8 passes) -> middle
// untangle/square/repack (bitrev-aware pairing) -> inv DIT (4 radix-8 passes).

#define SEQ_L   4096
#define OUT_L   (2 * SEQ_L - 1)     // 8191
#define FFT_M   4096
#define NT      512

#define IDX(a)  ((a) + ((a) >> 4))
#define RE_SZ   (FFT_M + (FFT_M >> 4))          // 4352
#define TW_SZ   ((FFT_M/2) + ((FFT_M/2) >> 4))  // 2176
#define S8      0.70710678118654752440f

extern __shared__ float s_mem[];

__global__ void __launch_bounds__(NT, 1)
conv_self_rfft8_kernel(const float* __restrict__ x, float* __restrict__ out) {
    float* re   = s_mem;
    float* im   = s_mem + RE_SZ;
    float* twre = s_mem + 2 * RE_SZ;
    float* twim = s_mem + 2 * RE_SZ + TW_SZ;

    const int tid = threadIdx.x;
    const int b   = blockIdx.x;

    // Twiddles: tw[t] = exp(-2*pi*i*t/M), t in [0, M/2)
    const float W_ANG = -6.28318530717958647692f / (float)FFT_M;
    #pragma unroll
    for (int t = tid; t < FFT_M / 2; t += NT) {
        float s, c;
        __sincosf(W_ANG * (float)t, &s, &c);
        twre[IDX(t)] = c;
        twim[IDX(t)] = s;
    }

    // Load packed input
    const float2* xb2 = (const float2*)(x + (size_t)b * SEQ_L);
    #pragma unroll
    for (int m = tid; m < FFT_M; m += NT) {
        if (m < SEQ_L / 2) {
            float2 v = xb2[m];
            re[IDX(m)] = v.x;
            im[IDX(m)] = v.y;
        } else {
            re[IDX(m)] = 0.0f;
            im[IDX(m)] = 0.0f;
        }
    }
    __syncthreads();

    // ---- Forward DIF, radix-8 fused: len in {4096, 512, 64, 8} ----
    #pragma unroll
    for (int len = FFT_M; len >= 8; len >>= 3) {
        const int q8 = len >> 3;
        const int st = FFT_M / len;
        const int p    = tid & (q8 - 1);
        const int base = ((tid - p) << 3) + p;

        int ix[8];
        #pragma unroll
        for (int k = 0; k < 8; k++) ix[k] = IDX(base + k * q8);

        float xr[8], xi[8];
        #pragma unroll
        for (int k = 0; k < 8; k++) { xr[k] = re[ix[k]]; xi[k] = im[ix[k]]; }

        const int t1 = p * st;
        const float w1r = twre[IDX(t1)], w1i = twim[IDX(t1)];
        const int t2 = t1 << 1;
        const float w2r = twre[IDX(t2)], w2i = twim[IDX(t2)];
        const int t4 = t1 << 2;
        const float w4r = twre[IDX(t4)], w4i = twim[IDX(t4)];

        // derived stage-1 twiddles: W1*E_k, E = [1, c8, -i, -i*c8], c8=exp(-i pi/4)
        const float wbr = S8 * (w1r + w1i), wbi = S8 * (w1i - w1r);   // W1*c8
        const float wcr = w1i,              wci = -w1r;               // -i*W1
        const float wdr = -S8 * (w1r - w1i), wdi = -S8 * (w1i + w1r); // -i*W1*c8

        // stage 1: pairs (k, k+4)
        float sr[4], si[4], dr[4], di[4];
        #pragma unroll
        for (int k = 0; k < 4; k++) {
            sr[k] = xr[k] + xr[k + 4];  si[k] = xi[k] + xi[k + 4];
            dr[k] = xr[k] - xr[k + 4];  di[k] = xi[k] - xi[k + 4];
        }
        xr[0] = sr[0]; xi[0] = si[0];
        xr[1] = sr[1]; xi[1] = si[1];
        xr[2] = sr[2]; xi[2] = si[2];
        xr[3] = sr[3]; xi[3] = si[3];
        xr[4] = dr[0] * w1r - di[0] * w1i;  xi[4] = dr[0] * w1i + di[0] * w1r;
        xr[5] = dr[1] * wbr - di[1] * wbi;  xi[5] = dr[1] * wbi + di[1] * wbr;
        xr[6] = dr[2] * wcr - di[2] * wci;  xi[6] = dr[2] * wci + di[2] * wcr;
        xr[7] = dr[3] * wdr - di[3] * wdi;  xi[7] = dr[3] * wdi + di[3] * wdr;

        // stage 2: in each half, pairs (0,2),(1,3); twiddles W2 and -i*W2
        #pragma unroll
        for (int h = 0; h < 8; h += 4) {
            float ur, ui;
            ur = xr[h + 0] - xr[h + 2]; ui = xi[h + 0] - xi[h + 2];
            xr[h + 0] += xr[h + 2];     xi[h + 0] += xi[h + 2];
            xr[h + 2] = ur * w2r - ui * w2i;
            xi[h + 2] = ur * w2i + ui * w2r;
            ur = xr[h + 1] - xr[h + 3]; ui = xi[h + 1] - xi[h + 3];
            xr[h + 1] += xr[h + 3];     xi[h + 1] += xi[h + 3];
            // * (-i*W2) = (w2i, -w2r)
            xr[h + 3] = ur * w2i + ui * w2r;
            xi[h + 3] = ui * w2i - ur * w2r;
        }

        // stage 3: pairs (2k, 2k+1), twiddle W4
        #pragma unroll
        for (int h = 0; h < 8; h += 2) {
            const float ur = xr[h] - xr[h + 1], ui = xi[h] - xi[h + 1];
            xr[h] += xr[h + 1];  xi[h] += xi[h + 1];
            xr[h + 1] = ur * w4r - ui * w4i;
            xi[h + 1] = ur * w4i + ui * w4r;
        }

        __syncthreads();   // WAR: everyone done reading before writeback?  No —
        // reads and writes are to the same slots owned by this thread only, so
        // no cross-thread hazard within a pass; barrier after writes suffices.
        #pragma unroll
        for (int k = 0; k < 8; k++) { re[ix[k]] = xr[k]; im[ix[k]] = xi[k]; }
        __syncthreads();
    }

    // ---- Middle: untangle + square + repack (bit-reversed order) ----
    const float N_ANG = -6.28318530717958647692f / (float)(2 * FFT_M);
    #pragma unroll
    for (int m = tid; m < FFT_M / 2; m += NT) {
        if (m == 0) {
            float zr = re[IDX(0)], zq = im[IDX(0)];
            float P = zr + zq, Q = zr - zq;
            float P2 = P * P, Q2 = Q * Q;
            re[IDX(0)] = 0.5f * (P2 + Q2);
            im[IDX(0)] = 0.5f * (P2 - Q2);
            zr = re[IDX(1)]; zq = im[IDX(1)];
            re[IDX(1)] = zr * zr - zq * zq;
            im[IDX(1)] = 2.0f * zr * zq;
        } else {
            const int msb = 1 << (31 - __clz(m));
            const int kb = m + msb;
            const int pb = 6 * msb - 1 - kb;
            const int k  = __brev((unsigned)kb) >> 20;

            float wi, wr;
            __sincosf(N_ANG * (float)k, &wi, &wr);

            const float zkr = re[IDX(kb)], zki = im[IDX(kb)];
            const float zmr = re[IDX(pb)], zmi = im[IDX(pb)];

            const float Er = 0.5f * (zkr + zmr);
            const float Ei = 0.5f * (zki - zmi);
            const float Or = 0.5f * (zki + zmi);
            const float Oi = 0.5f * (zmr - zkr);

            const float WOr = Or * wr - Oi * wi;
            const float WOi = Or * wi + Oi * wr;

            const float Pr = Er + WOr, Pi = Ei + WOi;
            const float Qr = Er - WOr, Qi = Ei - WOi;

            const float P2r = Pr * Pr - Pi * Pi, P2i = 2.0f * Pr * Pi;
            const float Q2r = Qr * Qr - Qi * Qi, Q2i = 2.0f * Qr * Qi;

            const float Epr = 0.5f * (P2r + Q2r);
            const float Epi = 0.5f * (P2i + Q2i);
            const float Sr  = 0.5f * (P2r - Q2r);
            const float Si  = 0.5f * (P2i - Q2i);
            const float Opr = Sr * wr + Si * wi;
            const float Opi = Si * wr - Sr * wi;

            re[IDX(kb)] = Epr - Opi;
            im[IDX(kb)] = Epi + Opr;
            re[IDX(pb)] = Epr + Opi;
            im[IDX(pb)] = Opr - Epi;
        }
    }
    __syncthreads();

    // ---- Inverse DIT, radix-8 fused: lenBig in {8, 64, 512, 4096} ----
    #pragma unroll
    for (int lenBig = 8; lenBig <= FFT_M; lenBig <<= 3) {
        const int q8 = lenBig >> 3;
        const int st = FFT_M / lenBig;
        const int p    = tid & (q8 - 1);
        const int base = ((tid - p) << 3) + p;

        int ix[8];
        #pragma unroll
        for (int k = 0; k < 8; k++) ix[k] = IDX(base + k * q8);

        float xr[8], xi[8];
        #pragma unroll
        for (int k = 0; k < 8; k++) { xr[k] = re[ix[k]]; xi[k] = im[ix[k]]; }

        const int t1 = p * st;
        const float w1r = twre[IDX(t1)], w1i = twim[IDX(t1)];
        const int t2 = t1 << 1;
        const float w2r = twre[IDX(t2)], w2i = twim[IDX(t2)];
        const int t4 = t1 << 2;
        const float w4r = twre[IDX(t4)], w4i = twim[IDX(t4)];

        // stage A: span q8, pairs (2k, 2k+1), multiply by conj(W4)
        #pragma unroll
        for (int h = 0; h < 8; h += 2) {
            const float tr = xr[h + 1] * w4r + xi[h + 1] * w4i;
            const float ti = xi[h + 1] * w4r - xr[h + 1] * w4i;
            xr[h + 1] = xr[h] - tr;  xi[h + 1] = xi[h] - ti;
            xr[h]    += tr;          xi[h]    += ti;
        }

        // stage B: span 2q8, pairs (0,2),(1,3) per half
        // (0,2): conj(W2); (1,3): conj(-i*W2) -> mult by (w2i + i*w2r)
        #pragma unroll
        for (int h = 0; h < 8; h += 4) {
            float tr, ti;
            tr = xr[h + 2] * w2r + xi[h + 2] * w2i;
            ti = xi[h + 2] * w2r - xr[h + 2] * w2i;
            xr[h + 2] = xr[h] - tr;  xi[h + 2] = xi[h] - ti;
            xr[h]    += tr;          xi[h]    += ti;
            tr = xr[h + 3] * w2i - xi[h + 3] * w2r;
            ti = xr[h + 3] * w2r + xi[h + 3] * w2i;
            xr[h + 3] = xr[h + 1] - tr;  xi[h + 3] = xi[h + 1] - ti;
            xr[h + 1] += tr;             xi[h + 1] += ti;
        }

        // stage C: span 4q8, pairs (k, k+4), twiddles conj(W1 * E_k)
        {
            float tr, ti;
            // k=0: conj(W1)
            tr = xr[4] * w1r + xi[4] * w1i;
            ti = xi[4] * w1r - xr[4] * w1i;
            xr[4] = xr[0] - tr;  xi[4] = xi[0] - ti;
            xr[0] += tr;         xi[0] += ti;
            // k=1: Wc1 = (S8*(w1r+w1i), S8*(w1r-w1i))
            const float c1r = S8 * (w1r + w1i), c1i = S8 * (w1r - w1i);
            tr = xr[5] * c1r - xi[5] * c1i;
            ti = xr[5] * c1i + xi[5] * c1r;
            xr[5] = xr[1] - tr;  xi[5] = xi[1] - ti;
            xr[1] += tr;         xi[1] += ti;
            // k=2: Wc2 = (w1i, w1r)
            tr = xr[6] * w1i - xi[6] * w1r;
            ti = xr[6] * w1r + xi[6] * w1i;
            xr[6] = xr[2] - tr;  xi[6] = xi[2] - ti;
            xr[2] += tr;         xi[2] += ti;
            // k=3: Wc3 = (-S8*(w1r-w1i), S8*(w1i+w1r))
            const float c3r = -S8 * (w1r - w1i), c3i = S8 * (w1i + w1r);
            tr = xr[7] * c3r - xi[7] * c3i;
            ti = xr[7] * c3i + xi[7] * c3r;
            xr[7] = xr[3] - tr;  xi[7] = xi[3] - ti;
            xr[3] += tr;         xi[3] += ti;
        }

        #pragma unroll
        for (int k = 0; k < 8; k++) { re[ix[k]] = xr[k]; im[ix[k]] = xi[k]; }
        __syncthreads();
    }

    // ---- Store: y[2m]=Re/M, y[2m+1]=Im/M ----
    const float invM = 1.0f / (float)FFT_M;
    float* ob = out + (size_t)b * OUT_L;
    #pragma unroll
    for (int m = tid; m < FFT_M; m += NT) {
        const int a = IDX(m);
        ob[2 * m] = re[a] * invM;
        if (2 * m + 1 < OUT_L)
            ob[2 * m + 1] = im[a] * invM;
    }
}

extern "C" void kernel_launch(void* const* d_in, const int* in_sizes, int n_in,
                              void* d_out, int out_size) {
    (void)in_sizes; (void)n_in; (void)out_size;
    const float* x = (const float*)d_in[0];
    float* out = (float*)d_out;

    const int smem_bytes = (2 * RE_SZ + 2 * TW_SZ) * (int)sizeof(float);  // ~51 KB
    cudaFuncSetAttribute(conv_self_rfft8_kernel,
                         cudaFuncAttributeMaxDynamicSharedMemorySize, smem_bytes);

    conv_self_rfft8_kernel<<<128, NT, smem_bytes>>>(x, out);
}

// round 4
// speedup vs baseline: 5.5550x; 1.0938x over previous
#include <cuda_runtime.h>
#include <math.h>

// Self-convolution via real-packed shared-memory FFT, radix-8 fused passes,
// float2-interleaved smem (one LDS.64/STS.64 per complex slot).
// out[b,t] = sum_i x[b,i]*x[b,t-i]; 8192-pt conv via M=4096 complex FFT of
// z[m]=x[2m]+i*x[2m+1]. Fwd DIF (4 radix-8 passes) -> middle untangle/square/
// repack (bitrev-aware) -> inv DIT (4 radix-8 passes).

#define SEQ_L   4096
#define OUT_L   (2 * SEQ_L - 1)     // 8191
#define FFT_M   4096
#define NT      512

#define IDX(a)  ((a) + ((a) >> 4))
#define RE_SZ   (FFT_M + (FFT_M >> 4))          // 4352 complex slots
#define TW_SZ   ((FFT_M/2) + ((FFT_M/2) >> 4))  // 2176 complex slots
#define S8      0.70710678118654752440f

__device__ __forceinline__ float2 cmul(float2 a, float2 w) {
    return make_float2(a.x * w.x - a.y * w.y, a.x * w.y + a.y * w.x);
}
__device__ __forceinline__ float2 cmulj(float2 a, float2 w) {  // a * conj(w)
    return make_float2(a.x * w.x + a.y * w.y, a.y * w.x - a.x * w.y);
}
__device__ __forceinline__ float2 cadd(float2 a, float2 b) {
    return make_float2(a.x + b.x, a.y + b.y);
}
__device__ __forceinline__ float2 csub(float2 a, float2 b) {
    return make_float2(a.x - b.x, a.y - b.y);
}

extern __shared__ float2 s_z[];

__global__ void __launch_bounds__(NT, 1)
conv_self_rfft8v_kernel(const float* __restrict__ x, float* __restrict__ out) {
    float2* z  = s_z;           // RE_SZ complex
    float2* tw = s_z + RE_SZ;   // TW_SZ complex

    const int tid = threadIdx.x;
    const int b   = blockIdx.x;

    // Twiddles: tw[t] = exp(-2*pi*i*t/M), t in [0, M/2)
    const float W_ANG = -6.28318530717958647692f / (float)FFT_M;
    #pragma unroll
    for (int t = tid; t < FFT_M / 2; t += NT) {
        float s, c;
        __sincosf(W_ANG * (float)t, &s, &c);
        tw[IDX(t)] = make_float2(c, s);
    }

    // Load packed input: z[m] = x[2m] + i*x[2m+1]; zero-pad m >= L/2
    const float2* xb2 = (const float2*)(x + (size_t)b * SEQ_L);
    #pragma unroll
    for (int m = tid; m < FFT_M; m += NT) {
        z[IDX(m)] = (m < SEQ_L / 2) ? xb2[m] : make_float2(0.0f, 0.0f);
    }
    __syncthreads();

    // ---- Forward DIF, radix-8 fused: len in {4096, 512, 64, 8} ----
    #pragma unroll
    for (int len = FFT_M; len >= 8; len >>= 3) {
        const int q8 = len >> 3;
        const int st = FFT_M / len;
        const int p    = tid & (q8 - 1);
        const int base = ((tid - p) << 3) + p;

        int ix[8];
        #pragma unroll
        for (int k = 0; k < 8; k++) ix[k] = IDX(base + k * q8);

        float2 v[8];
        #pragma unroll
        for (int k = 0; k < 8; k++) v[k] = z[ix[k]];

        const int t1 = p * st;
        const float2 w1 = tw[IDX(t1)];
        const float2 w2 = tw[IDX(t1 << 1)];
        const float2 w4 = tw[IDX(t1 << 2)];

        // stage-1 derived twiddles: W1*E_k, E = [1, c8, -i, -i*c8]
        const float2 wb = make_float2(S8 * (w1.x + w1.y), S8 * (w1.y - w1.x));
        const float2 wc = make_float2(w1.y, -w1.x);
        const float2 wd = make_float2(-S8 * (w1.x - w1.y), -S8 * (w1.y + w1.x));

        // stage 1: pairs (k, k+4)
        float2 s0 = cadd(v[0], v[4]), d0 = csub(v[0], v[4]);
        float2 s1 = cadd(v[1], v[5]), d1 = csub(v[1], v[5]);
        float2 s2 = cadd(v[2], v[6]), d2 = csub(v[2], v[6]);
        float2 s3 = cadd(v[3], v[7]), d3 = csub(v[3], v[7]);
        v[0] = s0; v[1] = s1; v[2] = s2; v[3] = s3;
        v[4] = cmul(d0, w1);
        v[5] = cmul(d1, wb);
        v[6] = cmul(d2, wc);
        v[7] = cmul(d3, wd);

        // stage 2: per half, pairs (0,2),(1,3); twiddles W2 and -i*W2
        #pragma unroll
        for (int h = 0; h < 8; h += 4) {
            float2 u = csub(v[h + 0], v[h + 2]);
            v[h + 0] = cadd(v[h + 0], v[h + 2]);
            v[h + 2] = cmul(u, w2);
            u = csub(v[h + 1], v[h + 3]);
            v[h + 1] = cadd(v[h + 1], v[h + 3]);
            // * (-i*W2) = (w2.y, -w2.x)
            v[h + 3] = make_float2(u.x * w2.y + u.y * w2.x,
                                   u.y * w2.y - u.x * w2.x);
        }

        // stage 3: pairs (2k, 2k+1), twiddle W4
        #pragma unroll
        for (int h = 0; h < 8; h += 2) {
            const float2 u = csub(v[h], v[h + 1]);
            v[h] = cadd(v[h], v[h + 1]);
            v[h + 1] = cmul(u, w4);
        }

        // thread-local slots: no pre-write barrier needed
        #pragma unroll
        for (int k = 0; k < 8; k++) z[ix[k]] = v[k];
        __syncthreads();
    }

    // ---- Middle: untangle + square + repack (bit-reversed order) ----
    const float N_ANG = -6.28318530717958647692f / (float)(2 * FFT_M);
    #pragma unroll
    for (int m = tid; m < FFT_M / 2; m += NT) {
        if (m == 0) {
            float2 z0 = z[IDX(0)];
            const float P = z0.x + z0.y, Q = z0.x - z0.y;
            const float P2 = P * P, Q2 = Q * Q;
            z[IDX(0)] = make_float2(0.5f * (P2 + Q2), 0.5f * (P2 - Q2));
            float2 z1 = z[IDX(1)];
            z[IDX(1)] = make_float2(z1.x * z1.x - z1.y * z1.y,
                                    2.0f * z1.x * z1.y);
        } else {
            const int msb = 1 << (31 - __clz(m));
            const int kb = m + msb;
            const int pb = 6 * msb - 1 - kb;
            const int k  = __brev((unsigned)kb) >> 20;

            float wi, wr;
            __sincosf(N_ANG * (float)k, &wi, &wr);

            const float2 zk = z[IDX(kb)];
            const float2 zm = z[IDX(pb)];

            const float Er = 0.5f * (zk.x + zm.x);
            const float Ei = 0.5f * (zk.y - zm.y);
            const float Or = 0.5f * (zk.y + zm.y);
            const float Oi = 0.5f * (zm.x - zk.x);

            const float WOr = Or * wr - Oi * wi;
            const float WOi = Or * wi + Oi * wr;

            const float Pr = Er + WOr, Pi = Ei + WOi;
            const float Qr = Er - WOr, Qi = Ei - WOi;

            const float P2r = Pr * Pr - Pi * Pi, P2i = 2.0f * Pr * Pi;
            const float Q2r = Qr * Qr - Qi * Qi, Q2i = 2.0f * Qr * Qi;

            const float Epr = 0.5f * (P2r + Q2r);
            const float Epi = 0.5f * (P2i + Q2i);
            const float Sr  = 0.5f * (P2r - Q2r);
            const float Si  = 0.5f * (P2i - Q2i);
            const float Opr = Sr * wr + Si * wi;
            const float Opi = Si * wr - Sr * wi;

            z[IDX(kb)] = make_float2(Epr - Opi, Epi + Opr);
            z[IDX(pb)] = make_float2(Epr + Opi, Opr - Epi);
        }
    }
    __syncthreads();

    // ---- Inverse DIT, radix-8 fused: lenBig in {8, 64, 512, 4096} ----
    #pragma unroll
    for (int lenBig = 8; lenBig <= FFT_M; lenBig <<= 3) {
        const int q8 = lenBig >> 3;
        const int st = FFT_M / lenBig;
        const int p    = tid & (q8 - 1);
        const int base = ((tid - p) << 3) + p;

        int ix[8];
        #pragma unroll
        for (int k = 0; k < 8; k++) ix[k] = IDX(base + k * q8);

        float2 v[8];
        #pragma unroll
        for (int k = 0; k < 8; k++) v[k] = z[ix[k]];

        const int t1 = p * st;
        const float2 w1 = tw[IDX(t1)];
        const float2 w2 = tw[IDX(t1 << 1)];
        const float2 w4 = tw[IDX(t1 << 2)];

        // stage A: pairs (2k, 2k+1), multiply by conj(W4)
        #pragma unroll
        for (int h = 0; h < 8; h += 2) {
            const float2 t = cmulj(v[h + 1], w4);
            v[h + 1] = csub(v[h], t);
            v[h]     = cadd(v[h], t);
        }

        // stage B: per half, (0,2): conj(W2); (1,3): mult by (w2.y + i*w2.x)
        #pragma unroll
        for (int h = 0; h < 8; h += 4) {
            float2 t = cmulj(v[h + 2], w2);
            v[h + 2] = csub(v[h], t);
            v[h]     = cadd(v[h], t);
            t = make_float2(v[h + 3].x * w2.y - v[h + 3].y * w2.x,
                            v[h + 3].x * w2.x + v[h + 3].y * w2.y);
            v[h + 3] = csub(v[h + 1], t);
            v[h + 1] = cadd(v[h + 1], t);
        }

        // stage C: pairs (k, k+4), twiddles conj(W1*E_k)
        {
            float2 t = cmulj(v[4], w1);
            v[4] = csub(v[0], t);
            v[0] = cadd(v[0], t);

            const float2 c1 = make_float2(S8 * (w1.x + w1.y), S8 * (w1.x - w1.y));
            t = cmul(v[5], c1);
            v[5] = csub(v[1], t);
            v[1] = cadd(v[1], t);

            t = make_float2(v[6].x * w1.y - v[6].y * w1.x,
                            v[6].x * w1.x + v[6].y * w1.y);
            v[6] = csub(v[2], t);
            v[2] = cadd(v[2], t);

            const float2 c3 = make_float2(-S8 * (w1.x - w1.y), S8 * (w1.y + w1.x));
            t = cmul(v[7], c3);
            v[7] = csub(v[3], t);
            v[3] = cadd(v[3], t);
        }

        #pragma unroll
        for (int k = 0; k < 8; k++) z[ix[k]] = v[k];
        __syncthreads();
    }

    // ---- Store: y[2m]=Re/M, y[2m+1]=Im/M ----
    const float invM = 1.0f / (float)FFT_M;
    float* ob = out + (size_t)b * OUT_L;
    #pragma unroll
    for (int m = tid; m < FFT_M; m += NT) {
        const float2 v = z[IDX(m)];
        ob[2 * m] = v.x * invM;
        if (2 * m + 1 < OUT_L)
            ob[2 * m + 1] = v.y * invM;
    }
}

extern "C" void kernel_launch(void* const* d_in, const int* in_sizes, int n_in,
                              void* d_out, int out_size) {
    (void)in_sizes; (void)n_in; (void)out_size;
    const float* x = (const float*)d_in[0];
    float* out = (float*)d_out;

    const int smem_bytes = (RE_SZ + TW_SZ) * (int)sizeof(float2);  // ~51 KB
    cudaFuncSetAttribute(conv_self_rfft8v_kernel,
                         cudaFuncAttributeMaxDynamicSharedMemorySize, smem_bytes);

    conv_self_rfft8v_kernel<<<128, NT, smem_bytes>>>(x, out);
}

// round 5
// speedup vs baseline: 6.1851x; 1.1134x over previous
#include <cuda_runtime.h>
#include <math.h>

// Self-convolution via real-packed shared-memory FFT, radix-8 fused passes,
// float2 smem, locality-scoped synchronization:
//   full CTA barriers only where butterflies span the whole array;
//   2-warp named barriers for 512-point spans; __syncwarp for 64-point spans;
//   nothing for thread-local passes (pass1 fwd, pass4 fwd->own slots,
//   passD inv -> store).

#define SEQ_L   4096
#define OUT_L   (2 * SEQ_L - 1)     // 8191
#define FFT_M   4096
#define NT      512

#define IDX(a)  ((a) + ((a) >> 4))
#define RE_SZ   (FFT_M + (FFT_M >> 4))          // 4352 complex slots
#define TW_SZ   ((FFT_M/2) + ((FFT_M/2) >> 4))  // 2176 complex slots
#define S8      0.70710678118654752440f

// 2-warp named barrier: threads 64i..64i+63 sync on id 1+i
#define BAR_PAIR(tid) asm volatile("bar.sync %0, 64;" :: "r"(1 + ((tid) >> 6)) : "memory")

__device__ __forceinline__ float2 cmul(float2 a, float2 w) {
    return make_float2(a.x * w.x - a.y * w.y, a.x * w.y + a.y * w.x);
}
__device__ __forceinline__ float2 cmulj(float2 a, float2 w) {  // a * conj(w)
    return make_float2(a.x * w.x + a.y * w.y, a.y * w.x - a.x * w.y);
}
__device__ __forceinline__ float2 cadd(float2 a, float2 b) {
    return make_float2(a.x + b.x, a.y + b.y);
}
__device__ __forceinline__ float2 csub(float2 a, float2 b) {
    return make_float2(a.x - b.x, a.y - b.y);
}

extern __shared__ float2 s_z[];

// One radix-8 DIF stage triple given twiddles (w1,w2,w4), in registers.
__device__ __forceinline__ void fwd8(float2 v[8], float2 w1, float2 w2, float2 w4) {
    const float2 wb = make_float2(S8 * (w1.x + w1.y), S8 * (w1.y - w1.x));
    const float2 wc = make_float2(w1.y, -w1.x);
    const float2 wd = make_float2(-S8 * (w1.x - w1.y), -S8 * (w1.y + w1.x));

    float2 s0 = cadd(v[0], v[4]), d0 = csub(v[0], v[4]);
    float2 s1 = cadd(v[1], v[5]), d1 = csub(v[1], v[5]);
    float2 s2 = cadd(v[2], v[6]), d2 = csub(v[2], v[6]);
    float2 s3 = cadd(v[3], v[7]), d3 = csub(v[3], v[7]);
    v[0] = s0; v[1] = s1; v[2] = s2; v[3] = s3;
    v[4] = cmul(d0, w1);
    v[5] = cmul(d1, wb);
    v[6] = cmul(d2, wc);
    v[7] = cmul(d3, wd);

    #pragma unroll
    for (int h = 0; h < 8; h += 4) {
        float2 u = csub(v[h + 0], v[h + 2]);
        v[h + 0] = cadd(v[h + 0], v[h + 2]);
        v[h + 2] = cmul(u, w2);
        u = csub(v[h + 1], v[h + 3]);
        v[h + 1] = cadd(v[h + 1], v[h + 3]);
        v[h + 3] = make_float2(u.x * w2.y + u.y * w2.x,
                               u.y * w2.y - u.x * w2.x);   // * (-i*W2)
    }

    #pragma unroll
    for (int h = 0; h < 8; h += 2) {
        const float2 u = csub(v[h], v[h + 1]);
        v[h] = cadd(v[h], v[h + 1]);
        v[h + 1] = cmul(u, w4);
    }
}

__device__ __forceinline__ void inv8(float2 v[8], float2 w1, float2 w2, float2 w4) {
    #pragma unroll
    for (int h = 0; h < 8; h += 2) {
        const float2 t = cmulj(v[h + 1], w4);
        v[h + 1] = csub(v[h], t);
        v[h]     = cadd(v[h], t);
    }
    #pragma unroll
    for (int h = 0; h < 8; h += 4) {
        float2 t = cmulj(v[h + 2], w2);
        v[h + 2] = csub(v[h], t);
        v[h]     = cadd(v[h], t);
        t = make_float2(v[h + 3].x * w2.y - v[h + 3].y * w2.x,
                        v[h + 3].x * w2.x + v[h + 3].y * w2.y);
        v[h + 3] = csub(v[h + 1], t);
        v[h + 1] = cadd(v[h + 1], t);
    }
    {
        float2 t = cmulj(v[4], w1);
        v[4] = csub(v[0], t);
        v[0] = cadd(v[0], t);

        const float2 c1 = make_float2(S8 * (w1.x + w1.y), S8 * (w1.x - w1.y));
        t = cmul(v[5], c1);
        v[5] = csub(v[1], t);
        v[1] = cadd(v[1], t);

        t = make_float2(v[6].x * w1.y - v[6].y * w1.x,
                        v[6].x * w1.x + v[6].y * w1.y);
        v[6] = csub(v[2], t);
        v[2] = cadd(v[2], t);

        const float2 c3 = make_float2(-S8 * (w1.x - w1.y), S8 * (w1.y + w1.x));
        t = cmul(v[7], c3);
        v[7] = csub(v[3], t);
        v[3] = cadd(v[3], t);
    }
}

__global__ void __launch_bounds__(NT, 1)
conv_self_rfft8s_kernel(const float* __restrict__ x, float* __restrict__ out) {
    float2* z  = s_z;           // RE_SZ complex
    float2* tw = s_z + RE_SZ;   // TW_SZ complex

    const int tid = threadIdx.x;
    const int b   = blockIdx.x;

    // Twiddle table (consumed from pass2 onward; pass1's barrier orders it)
    const float W_ANG = -6.28318530717958647692f / (float)FFT_M;
    #pragma unroll
    for (int t = tid; t < FFT_M / 2; t += NT) {
        float s, c;
        __sincosf(W_ANG * (float)t, &s, &c);
        tw[IDX(t)] = make_float2(c, s);
    }

    // Load packed input into this thread's pass-1 slots (m = tid + 512k)
    const float2* xb2 = (const float2*)(x + (size_t)b * SEQ_L);
    #pragma unroll
    for (int m = tid; m < FFT_M; m += NT) {
        z[IDX(m)] = (m < SEQ_L / 2) ? xb2[m] : make_float2(0.0f, 0.0f);
    }
    // no barrier: pass1 touches exactly the slots this thread just wrote

    // ---- fwd pass1: len=4096, q8=512, thread-local slots; sincosf twiddles
    {
        float2 v[8];
        #pragma unroll
        for (int k = 0; k < 8; k++) v[k] = z[IDX(tid + k * 512)];
        float2 w1;
        __sincosf(W_ANG * (float)tid, &w1.y, &w1.x);
        const float2 w2 = cmul(w1, w1);
        const float2 w4 = cmul(w2, w2);
        fwd8(v, w1, w2, w4);
        #pragma unroll
        for (int k = 0; k < 8; k++) z[IDX(tid + k * 512)] = v[k];
    }
    __syncthreads();

    // ---- fwd pass2: len=512 (spans 512 = 64-thread groups)
    {
        const int q8 = 64, st = 8;
        const int p = tid & (q8 - 1);
        const int base = ((tid - p) << 3) + p;
        int ix[8];
        #pragma unroll
        for (int k = 0; k < 8; k++) ix[k] = IDX(base + k * q8);
        float2 v[8];
        #pragma unroll
        for (int k = 0; k < 8; k++) v[k] = z[ix[k]];
        const int t1 = p * st;
        fwd8(v, tw[IDX(t1)], tw[IDX(t1 << 1)], tw[IDX(t1 << 2)]);
        #pragma unroll
        for (int k = 0; k < 8; k++) z[ix[k]] = v[k];
    }
    BAR_PAIR(tid);

    // ---- fwd pass3: len=64 (warp-contained)
    {
        const int q8 = 8, st = 64;
        const int p = tid & (q8 - 1);
        const int base = ((tid - p) << 3) + p;
        int ix[8];
        #pragma unroll
        for (int k = 0; k < 8; k++) ix[k] = IDX(base + k * q8);
        float2 v[8];
        #pragma unroll
        for (int k = 0; k < 8; k++) v[k] = z[ix[k]];
        const int t1 = p * st;
        fwd8(v, tw[IDX(t1)], tw[IDX(t1 << 1)], tw[IDX(t1 << 2)]);
        #pragma unroll
        for (int k = 0; k < 8; k++) z[ix[k]] = v[k];
    }
    __syncwarp();

    // ---- fwd pass4: len=8, contiguous [8t, 8t+8), twiddles = 1
    {
        const int base = tid << 3;
        int ix[8];
        #pragma unroll
        for (int k = 0; k < 8; k++) ix[k] = IDX(base + k);
        float2 v[8];
        #pragma unroll
        for (int k = 0; k < 8; k++) v[k] = z[ix[k]];
        fwd8(v, make_float2(1.f, 0.f), make_float2(1.f, 0.f), make_float2(1.f, 0.f));
        #pragma unroll
        for (int k = 0; k < 8; k++) z[ix[k]] = v[k];
    }
    __syncthreads();

    // ---- Middle: untangle + square + repack, scaled by 1/M ----
    const float N_ANG = -6.28318530717958647692f / (float)(2 * FFT_M);
    const float invM = 1.0f / (float)FFT_M;
    #pragma unroll
    for (int m = tid; m < FFT_M / 2; m += NT) {
        if (m == 0) {
            float2 z0 = z[IDX(0)];
            const float P = z0.x + z0.y, Q = z0.x - z0.y;
            const float P2 = P * P, Q2 = Q * Q;
            z[IDX(0)] = make_float2(0.5f * invM * (P2 + Q2),
                                    0.5f * invM * (P2 - Q2));
            float2 z1 = z[IDX(1)];
            z[IDX(1)] = make_float2(invM * (z1.x * z1.x - z1.y * z1.y),
                                    invM * (2.0f * z1.x * z1.y));
        } else {
            const int msb = 1 << (31 - __clz(m));
            const int kb = m + msb;
            const int pb = 6 * msb - 1 - kb;
            const int k  = __brev((unsigned)kb) >> 20;

            float wi, wr;
            __sincosf(N_ANG * (float)k, &wi, &wr);

            const float2 zk = z[IDX(kb)];
            const float2 zm = z[IDX(pb)];

            const float Er = 0.5f * (zk.x + zm.x);
            const float Ei = 0.5f * (zk.y - zm.y);
            const float Or = 0.5f * (zk.y + zm.y);
            const float Oi = 0.5f * (zm.x - zk.x);

            const float WOr = Or * wr - Oi * wi;
            const float WOi = Or * wi + Oi * wr;

            const float Pr = Er + WOr, Pi = Ei + WOi;
            const float Qr = Er - WOr, Qi = Ei - WOi;

            const float P2r = Pr * Pr - Pi * Pi, P2i = 2.0f * Pr * Pi;
            const float Q2r = Qr * Qr - Qi * Qi, Q2i = 2.0f * Qr * Qi;

            const float hm = 0.5f * invM;
            const float Epr = hm * (P2r + Q2r);
            const float Epi = hm * (P2i + Q2i);
            const float Sr  = hm * (P2r - Q2r);
            const float Si  = hm * (P2i - Q2i);
            const float Opr = Sr * wr + Si * wi;
            const float Opi = Si * wr - Sr * wi;

            z[IDX(kb)] = make_float2(Epr - Opi, Epi + Opr);
            z[IDX(pb)] = make_float2(Epr + Opi, Opr - Epi);
        }
    }
    __syncthreads();

    // ---- inv passA: lenBig=8, contiguous, twiddles = 1
    {
        const int base = tid << 3;
        int ix[8];
        #pragma unroll
        for (int k = 0; k < 8; k++) ix[k] = IDX(base + k);
        float2 v[8];
        #pragma unroll
        for (int k = 0; k < 8; k++) v[k] = z[ix[k]];
        inv8(v, make_float2(1.f, 0.f), make_float2(1.f, 0.f), make_float2(1.f, 0.f));
        #pragma unroll
        for (int k = 0; k < 8; k++) z[ix[k]] = v[k];
    }
    __syncwarp();

    // ---- inv passB: lenBig=64 (warp-contained)
    {
        const int q8 = 8, st = 64;
        const int p = tid & (q8 - 1);
        const int base = ((tid - p) << 3) + p;
        int ix[8];
        #pragma unroll
        for (int k = 0; k < 8; k++) ix[k] = IDX(base + k * q8);
        float2 v[8];
        #pragma unroll
        for (int k = 0; k < 8; k++) v[k] = z[ix[k]];
        const int t1 = p * st;
        inv8(v, tw[IDX(t1)], tw[IDX(t1 << 1)], tw[IDX(t1 << 2)]);
        #pragma unroll
        for (int k = 0; k < 8; k++) z[ix[k]] = v[k];
    }
    BAR_PAIR(tid);

    // ---- inv passC: lenBig=512 (64-thread groups)
    {
        const int q8 = 64, st = 8;
        const int p = tid & (q8 - 1);
        const int base = ((tid - p) << 3) + p;
        int ix[8];
        #pragma unroll
        for (int k = 0; k < 8; k++) ix[k] = IDX(base + k * q8);
        float2 v[8];
        #pragma unroll
        for (int k = 0; k < 8; k++) v[k] = z[ix[k]];
        const int t1 = p * st;
        inv8(v, tw[IDX(t1)], tw[IDX(t1 << 1)], tw[IDX(t1 << 2)]);
        #pragma unroll
        for (int k = 0; k < 8; k++) z[ix[k]] = v[k];
    }
    __syncthreads();

    // ---- inv passD: lenBig=4096, thread-local slots (tid + 512k); sincosf tw
    float2 v[8];
    {
        #pragma unroll
        for (int k = 0; k < 8; k++) v[k] = z[IDX(tid + k * 512)];
        float2 w1;
        __sincosf(W_ANG * (float)tid, &w1.y, &w1.x);
        const float2 w2 = cmul(w1, w1);
        const float2 w4 = cmul(w2, w2);
        inv8(v, w1, w2, w4);
    }
    // no barrier: store reads exactly this thread's v[] (slots tid + 512k)

    // ---- Store: y[2m]=Re, y[2m+1]=Im (already scaled) ----
    float* ob = out + (size_t)b * OUT_L;
    #pragma unroll
    for (int k = 0; k < 8; k++) {
        const int m = tid + k * 512;
        ob[2 * m] = v[k].x;
        if (2 * m + 1 < OUT_L)
            ob[2 * m + 1] = v[k].y;
    }
}

extern "C" void kernel_launch(void* const* d_in, const int* in_sizes, int n_in,
                              void* d_out, int out_size) {
    (void)in_sizes; (void)n_in; (void)out_size;
    const float* x = (const float*)d_in[0];
    float* out = (float*)d_out;

    const int smem_bytes = (RE_SZ + TW_SZ) * (int)sizeof(float2);  // ~51 KB
    cudaFuncSetAttribute(conv_self_rfft8s_kernel,
                         cudaFuncAttributeMaxDynamicSharedMemorySize, smem_bytes);

    conv_self_rfft8s_kernel<<<128, NT, smem_bytes>>>(x, out);
}